// round 16
// baseline (speedup 1.0000x reference)
#include <cuda_runtime.h>

// Problem constants
#define TT    1200              // time length
#define NF    10                // conv filters
#define KK    17                // conv kernel width (pad 8 both sides)
#define NSTR  240               // 5-wide output strips per row (1200/5)
#define NTP   76                // pooled length
#define NTPG  19                // groups of 4 pooled outputs (76/4)
#define FEAT  (NF*NTP)          // 760
#define ROWS  2                 // (b,m) rows per block (the f32x2 SIMD pair)
#define THREADS 256

typedef unsigned long long u64;

__device__ __forceinline__ u64 pack2(float lo, float hi) {
    u64 r;
    asm("mov.b64 %0, {%1, %2};" : "=l"(r) : "f"(lo), "f"(hi));
    return r;
}
__device__ __forceinline__ void unpack2(u64 v, float& lo, float& hi) {
    asm("mov.b64 {%0, %1}, %2;" : "=f"(lo), "=f"(hi) : "l"(v));
}
__device__ __forceinline__ u64 ffma2(u64 a, u64 b, u64 c) {
    u64 d;
    asm("fma.rn.f32x2 %0, %1, %2, %3;" : "=l"(d) : "l"(a), "l"(b), "l"(c));
    return d;
}

__global__ __launch_bounds__(THREADS, 4) void scorer_kernel(
    const float* __restrict__ x,       // (B,1,M,T) rows of 1200
    const float* __restrict__ conv_w,  // (NF,1,KK)
    const float* __restrict__ conv_b,  // (NF)
    const float* __restrict__ lin_w,   // (M, FEAT)
    const float* __restrict__ lin_b,   // (M)
    float* __restrict__ out)           // (B,M,1)
{
    __shared__ u64 s_x2[TT + 16];                       // {row0,row1} pairs, 8-zero halo
    __shared__ __align__(16) ulonglong2 s_w4[5 * KK];   // [pair p][k]: {dup w2p, dup w2p+1}
    __shared__ u64   s_b2[NF];                          // {b,b}
    __shared__ float s_S[ROWS][NF * NSTR];              // 5-strip sums of conv^2
    __shared__ float s_lin[ROWS][FEAT];                 // lin_w rows for this block
    __shared__ float s_out[ROWS];

    const int tid  = threadIdx.x;
    const int row0 = blockIdx.x * ROWS;    // row = b*64 + m
    const int m0   = row0 & 63;

    // ---- Phase 0: stage weights (pair-packed), bias, halos, x rows, lin_w rows ----
    for (int i = tid; i < 5 * KK; i += THREADS) {
        const int p = i / KK, k = i - p * KK;
        const float wa = conv_w[(2 * p)     * KK + k];
        const float wb = conv_w[(2 * p + 1) * KK + k];
        ulonglong2 v; v.x = pack2(wa, wa); v.y = pack2(wb, wb);
        s_w4[i] = v;
    }
    if (tid < NF)   { float b = conv_b[tid]; s_b2[tid] = pack2(b, b); }
    if (tid < ROWS) s_out[tid] = 0.f;
    if (tid >= THREADS - 16) {
        int j = tid - (THREADS - 16);
        if (j < 8) s_x2[j] = 0ull;             // left halo
        else       s_x2[TT + j] = 0ull;        // right halo
    }
    {
        const float* xr0 = x + (size_t)row0 * TT;
        const float* xr1 = xr0 + TT;
        for (int t = tid; t < TT; t += THREADS)
            s_x2[8 + t] = pack2(xr0[t], xr1[t]);   // coalesced within each row
    }
    {
        const float* l0 = lin_w + (size_t)m0 * FEAT;
        for (int i = tid; i < ROWS * FEAT; i += THREADS) {
            const int r = i / FEAT, c = i - r * FEAT;
            s_lin[r][c] = l0[(size_t)r * FEAT + c];
        }
    }
    __syncthreads();

    // ---- Phase 1: per strip, filter pairs, two half-tap passes (small reg window) ----
    if (tid < NSTR) {
        const int s = tid;
        const u64* xp = &s_x2[5 * s];          // xp[i] = x(t = 5s - 8 + i)

        #pragma unroll 1
        for (int p = 0; p < 5; ++p) {          // filters f0=2p, f1=2p+1
            const ulonglong2* wp = &s_w4[p * KK];
            u64 a0 = s_b2[2 * p],     a1 = a0, a2 = a0, a3 = a0, a4 = a0;
            u64 d0 = s_b2[2 * p + 1], d1 = d0, d2 = d0, d3 = d0, d4 = d0;

            {   // half A: taps 0..7, window xp[0..12]
                u64 xv[13];
                #pragma unroll
                for (int i = 0; i < 13; ++i) xv[i] = xp[i];
                #pragma unroll
                for (int k = 0; k < 8; ++k) {
                    const ulonglong2 wk = wp[k];   // one LDS.128: both filters
                    a0 = ffma2(xv[k    ], wk.x, a0);
                    a1 = ffma2(xv[k + 1], wk.x, a1);
                    a2 = ffma2(xv[k + 2], wk.x, a2);
                    a3 = ffma2(xv[k + 3], wk.x, a3);
                    a4 = ffma2(xv[k + 4], wk.x, a4);
                    d0 = ffma2(xv[k    ], wk.y, d0);
                    d1 = ffma2(xv[k + 1], wk.y, d1);
                    d2 = ffma2(xv[k + 2], wk.y, d2);
                    d3 = ffma2(xv[k + 3], wk.y, d3);
                    d4 = ffma2(xv[k + 4], wk.y, d4);
                }
            }
            {   // half B: taps 8..16, window xp[8..20]
                u64 xv[13];
                #pragma unroll
                for (int i = 0; i < 13; ++i) xv[i] = xp[8 + i];
                #pragma unroll
                for (int k = 8; k < KK; ++k) {
                    const ulonglong2 wk = wp[k];
                    const int b = k - 8;
                    a0 = ffma2(xv[b    ], wk.x, a0);
                    a1 = ffma2(xv[b + 1], wk.x, a1);
                    a2 = ffma2(xv[b + 2], wk.x, a2);
                    a3 = ffma2(xv[b + 3], wk.x, a3);
                    a4 = ffma2(xv[b + 4], wk.x, a4);
                    d0 = ffma2(xv[b    ], wk.y, d0);
                    d1 = ffma2(xv[b + 1], wk.y, d1);
                    d2 = ffma2(xv[b + 2], wk.y, d2);
                    d3 = ffma2(xv[b + 3], wk.y, d3);
                    d4 = ffma2(xv[b + 4], wk.y, d4);
                }
            }
            u64 Sa = ffma2(a0, a0, 0ull);
            Sa = ffma2(a1, a1, Sa);
            Sa = ffma2(a2, a2, Sa);
            Sa = ffma2(a3, a3, Sa);
            Sa = ffma2(a4, a4, Sa);
            u64 Sb = ffma2(d0, d0, 0ull);
            Sb = ffma2(d1, d1, Sb);
            Sb = ffma2(d2, d2, Sb);
            Sb = ffma2(d3, d3, Sb);
            Sb = ffma2(d4, d4, Sb);
            float v0, v1;
            unpack2(Sa, v0, v1);
            s_S[0][(2 * p)     * NSTR + s] = v0;
            s_S[1][(2 * p)     * NSTR + s] = v1;
            unpack2(Sb, v0, v1);
            s_S[0][(2 * p + 1) * NSTR + s] = v0;
            s_S[1][(2 * p + 1) * NSTR + s] = v1;
        }
    }
    __syncthreads();

    // ---- Phase 2: sliding pool (15 strips per window, hop 3) -> log -> dot ----
    float part0 = 0.f, part1 = 0.f;
    for (int task = tid; task < ROWS * NF * NTPG; task += THREADS) {   // 380 tasks
        int r   = task / (NF * NTPG);
        int rem = task - r * (NF * NTPG);
        int f   = rem / NTPG;
        int g   = rem - f * NTPG;              // covers tp = 4g .. 4g+3

        const float* Sp = &s_S[r][f * NSTR + 12 * g];
        float sv[24];
        #pragma unroll
        for (int j = 0; j < 24; ++j) sv[j] = Sp[j];

        float run = 0.f;
        #pragma unroll
        for (int j = 0; j < 15; ++j) run += sv[j];

        const float4 lw = *(const float4*)&s_lin[r][f * NTP + 4 * g];
        float acc = 0.f;
        #pragma unroll
        for (int q = 0; q < 4; ++q) {
            float pp = fmaxf(run * (1.0f / 75.0f), 1e-10f);
            float v = __logf(pp);
            float w = (q == 0) ? lw.x : (q == 1) ? lw.y : (q == 2) ? lw.z : lw.w;
            acc = fmaf(v, w, acc);
            if (q < 3) {
                run += (sv[15 + 3*q] + sv[16 + 3*q] + sv[17 + 3*q])
                     - (sv[3*q] + sv[1 + 3*q] + sv[2 + 3*q]);
            }
        }
        if (r == 0) part0 += acc; else part1 += acc;
    }
    #pragma unroll
    for (int off = 16; off > 0; off >>= 1) {
        part0 += __shfl_down_sync(0xffffffffu, part0, off);
        part1 += __shfl_down_sync(0xffffffffu, part1, off);
    }
    if ((tid & 31) == 0) {
        atomicAdd(&s_out[0], part0);
        atomicAdd(&s_out[1], part1);
    }
    __syncthreads();

    if (tid < ROWS) out[row0 + tid] = s_out[tid] + lin_b[m0 + tid];
}

extern "C" void kernel_launch(void* const* d_in, const int* in_sizes, int n_in,
                              void* d_out, int out_size) {
    const float* x      = (const float*)d_in[0];
    const float* conv_w = (const float*)d_in[1];
    const float* conv_b = (const float*)d_in[2];
    const float* lin_w  = (const float*)d_in[3];
    const float* lin_b  = (const float*)d_in[4];
    float* out = (float*)d_out;

    const int n_rows = 256 * 64;               // B*M
    scorer_kernel<<<n_rows / ROWS, THREADS>>>(x, conv_w, conv_b, lin_w, lin_b, out);
}